// round 1
// baseline (speedup 1.0000x reference)
#include <cuda_runtime.h>
#include <stdint.h>

#define N_ROWS 16384
#define K_DIM  200
#define H_DIM  768
#define NB_AUG 10

// ---------------- scratch (static device globals; no allocations) ----------
__device__ float g_x[(size_t)N_ROWS * K_DIM];   // fc output
__device__ float g_mu[K_DIM];
__device__ float g_sd[K_DIM];                   // sqrt(var + 1e-5)

// ---------------- threefry2x32 (JAX-exact) ---------------------------------
__device__ __forceinline__ uint2 tf2x32(uint32_t k0, uint32_t k1,
                                        uint32_t x0, uint32_t x1) {
    uint32_t ks2 = k0 ^ k1 ^ 0x1BD11BDAu;
    x0 += k0; x1 += k1;
#define TFR(r) { x0 += x1; x1 = __funnelshift_l(x1, x1, (r)); x1 ^= x0; }
    TFR(13) TFR(15) TFR(26) TFR(6)
    x0 += k1;  x1 += ks2 + 1u;
    TFR(17) TFR(29) TFR(16) TFR(24)
    x0 += ks2; x1 += k0 + 2u;
    TFR(13) TFR(15) TFR(26) TFR(6)
    x0 += k0;  x1 += k1 + 3u;
    TFR(17) TFR(29) TFR(16) TFR(24)
    x0 += k1;  x1 += ks2 + 4u;
    TFR(13) TFR(15) TFR(26) TFR(6)
    x0 += ks2; x1 += k0 + 5u;
#undef TFR
    return make_uint2(x0, x1);
}

// bits -> float in [0,1): ((bits>>9)|0x3f800000) bitcast - 1.0
__device__ __forceinline__ float bits_to_f01(uint32_t bits) {
    return __fsub_rn(__uint_as_float((bits >> 9) | 0x3f800000u), 1.0f);
}

// ---------------- XLA/Giles erfinv (f32), no FMA contraction ---------------
__device__ __forceinline__ float erfinv_xla(float x) {
    float w = -log1pf(-__fmul_rn(x, x));
    float p;
    if (w < 5.0f) {
        w = __fsub_rn(w, 2.5f);
        p = 2.81022636e-08f;
        p = __fadd_rn( 3.43273939e-07f, __fmul_rn(p, w));
        p = __fadd_rn(-3.5233877e-06f,  __fmul_rn(p, w));
        p = __fadd_rn(-4.39150654e-06f, __fmul_rn(p, w));
        p = __fadd_rn( 0.00021858087f,  __fmul_rn(p, w));
        p = __fadd_rn(-0.00125372503f,  __fmul_rn(p, w));
        p = __fadd_rn(-0.00417768164f,  __fmul_rn(p, w));
        p = __fadd_rn( 0.246640727f,    __fmul_rn(p, w));
        p = __fadd_rn( 1.50140941f,     __fmul_rn(p, w));
    } else {
        w = __fsub_rn(sqrtf(w), 3.0f);
        p = -0.000200214257f;
        p = __fadd_rn( 0.000100950558f, __fmul_rn(p, w));
        p = __fadd_rn( 0.00134934322f,  __fmul_rn(p, w));
        p = __fadd_rn(-0.00367342844f,  __fmul_rn(p, w));
        p = __fadd_rn( 0.00573950773f,  __fmul_rn(p, w));
        p = __fadd_rn(-0.0076224613f,   __fmul_rn(p, w));
        p = __fadd_rn( 0.00943887047f,  __fmul_rn(p, w));
        p = __fadd_rn( 1.00167406f,     __fmul_rn(p, w));
        p = __fadd_rn( 2.83297682f,     __fmul_rn(p, w));
    }
    return __fmul_rn(p, x);
}

// scalar normal from a key (JAX: sqrt2 * erfinv(uniform(lo=-0.99999994, hi=1)))
__device__ __forceinline__ float jax_normal_from_key(uint2 k) {
    uint2 nb = tf2x32(k.x, k.y, 0u, 0u);
    float f = bits_to_f01(nb.x ^ nb.y);
    float u = fmaxf(-0.99999994f, __fadd_rn(__fmul_rn(f, 2.0f), -0.99999994f));
    return __fmul_rn(__uint_as_float(0x3FB504F3u) /* sqrt(2) f32 */, erfinv_xla(u));
}

// ---------------- JAX gamma sampler (Marsaglia-Tsang, alpha >= 1) ----------
// flat element index i: per-element key Ki = TF((0,42),(0,i))  [partitionable split]
__device__ float jax_gamma(float aB, uint32_t i) {
    uint2 Ki  = tf2x32(0u, 42u, 0u, i);
    // prologue: key, subkey = split(Ki); subkey feeds unused u_boost (alpha>=1)
    uint2 key = tf2x32(Ki.x, Ki.y, 0u, 0u);

    float d = __fsub_rn(aB, 0.33333334f);
    float c = __fdiv_rn(0.33333334f, sqrtf(d));
    float V = 1.0f;

    for (;;) {
        // key, x_key, U_key = split(key, 3): children (0,0),(0,1),(0,2)
        uint2 xkey = tf2x32(key.x, key.y, 0u, 1u);
        uint2 Ukey = tf2x32(key.x, key.y, 0u, 2u);
        float x, v;
        uint2 ik = xkey;
        for (;;) {
            uint2 sub = tf2x32(ik.x, ik.y, 0u, 1u);  // (chain, subkey) = split(ik)
            x = jax_normal_from_key(sub);
            v = __fadd_rn(1.0f, __fmul_rn(x, c));
            if (v > 0.0f) break;
            ik = tf2x32(ik.x, ik.y, 0u, 0u);         // continue chain (v <= 0)
        }
        float X = __fmul_rn(x, x);
        V = __fmul_rn(__fmul_rn(v, v), v);
        uint2 ub = tf2x32(Ukey.x, Ukey.y, 0u, 0u);
        float U = bits_to_f01(ub.x ^ ub.y);

        // accept if U < 1 - 0.0331*X^2  (squeeze)
        float sq = __fsub_rn(1.0f, __fmul_rn(0.0331f, __fmul_rn(X, X)));
        if (U < sq) break;
        // accept if log U < 0.5*X + d - d*V + d*log V
        float rhs = __fadd_rn(__fmul_rn(X, 0.5f),
                    __fadd_rn(__fsub_rn(d, __fmul_rn(d, V)), __fmul_rn(d, logf(V))));
        if (logf(U) < rhs) break;
        key = tf2x32(key.x, key.y, 0u, 0u);          // reject: continue outer chain
    }
    float z = __fmul_rn(d, V);
    return (z == 0.0f) ? 1.17549435e-38f : z;
}

// ---------------- SGEMM: g_x = hidden(16384x768) * W(200x768)^T + b --------
__global__ void __launch_bounds__(256)
gemm_kernel(const float* __restrict__ A, const float* __restrict__ Wm,
            const float* __restrict__ bias) {
    const int BM = 128, BN = 64, BK = 16;
    __shared__ float As[BK][BM];
    __shared__ float Bs[BK][BN];
    int m0 = blockIdx.y * BM;
    int n0 = blockIdx.x * BN;
    int tid = threadIdx.x;
    int tx = tid & 15;   // n
    int ty = tid >> 4;   // m
    float acc[8][4];
#pragma unroll
    for (int i = 0; i < 8; i++)
#pragma unroll
        for (int j = 0; j < 4; j++) acc[i][j] = 0.0f;

    for (int h0 = 0; h0 < H_DIM; h0 += BK) {
#pragma unroll
        for (int q = 0; q < 2; q++) {
            int idx = tid * 2 + q;          // 0..511
            int r = idx >> 2, c4 = idx & 3;
            float4 av = *reinterpret_cast<const float4*>(
                &A[(size_t)(m0 + r) * H_DIM + h0 + c4 * 4]);
            As[c4 * 4 + 0][r] = av.x; As[c4 * 4 + 1][r] = av.y;
            As[c4 * 4 + 2][r] = av.z; As[c4 * 4 + 3][r] = av.w;
        }
        {
            int r = tid >> 2, c4 = tid & 3;
            float4 bv = make_float4(0.f, 0.f, 0.f, 0.f);
            if (n0 + r < K_DIM)
                bv = *reinterpret_cast<const float4*>(
                    &Wm[(size_t)(n0 + r) * H_DIM + h0 + c4 * 4]);
            Bs[c4 * 4 + 0][r] = bv.x; Bs[c4 * 4 + 1][r] = bv.y;
            Bs[c4 * 4 + 2][r] = bv.z; Bs[c4 * 4 + 3][r] = bv.w;
        }
        __syncthreads();
#pragma unroll
        for (int kk = 0; kk < BK; kk++) {
            float a[8], bb[4];
#pragma unroll
            for (int i = 0; i < 8; i++) a[i] = As[kk][ty * 8 + i];
#pragma unroll
            for (int j = 0; j < 4; j++) bb[j] = Bs[kk][tx * 4 + j];
#pragma unroll
            for (int i = 0; i < 8; i++)
#pragma unroll
                for (int j = 0; j < 4; j++)
                    acc[i][j] = fmaf(a[i], bb[j], acc[i][j]);
        }
        __syncthreads();
    }
#pragma unroll
    for (int i = 0; i < 8; i++) {
        int m = m0 + ty * 8 + i;
#pragma unroll
        for (int j = 0; j < 4; j++) {
            int nn = n0 + tx * 4 + j;
            if (nn < K_DIM)
                g_x[(size_t)m * K_DIM + nn] = acc[i][j] + bias[nn];
        }
    }
}

// ---------------- per-column mean / std (two-pass, like jnp.mean/var) ------
__global__ void __launch_bounds__(256) colstats_kernel() {
    int k = blockIdx.x;
    int t = threadIdx.x;
    __shared__ float sm[256];
    float s = 0.0f;
    for (int n = t; n < N_ROWS; n += 256) s += g_x[(size_t)n * K_DIM + k];
    sm[t] = s; __syncthreads();
    for (int st = 128; st > 0; st >>= 1) {
        if (t < st) sm[t] += sm[t + st];
        __syncthreads();
    }
    float mu = sm[0] / 16384.0f;
    __syncthreads();
    float v = 0.0f;
    for (int n = t; n < N_ROWS; n += 256) {
        float dd = g_x[(size_t)n * K_DIM + k] - mu;
        v += dd * dd;
    }
    sm[t] = v; __syncthreads();
    for (int st = 128; st > 0; st >>= 1) {
        if (t < st) sm[t] += sm[t + st];
        __syncthreads();
    }
    if (t == 0) {
        g_mu[k] = mu;
        g_sd[k] = sqrtf(sm[0] / 16384.0f + 1e-5f);
    }
}

// ---------------- fused: softplus -> gamma -> u-pow product -> rownorm -----
__global__ void __launch_bounds__(256)
main_kernel(const float* __restrict__ u, float* __restrict__ out) {
    int n = blockIdx.x;
    int k = threadIdx.x;
    float g = 0.0f;

    if (k < K_DIM) {
        float xv = g_x[(size_t)n * K_DIM + k];
        float xn = __fdiv_rn(__fsub_rn(xv, g_mu[k]), g_sd[k]);
        // softplus = max(x,0) + log1p(exp(-|x|))
        float sp = __fadd_rn(fmaxf(xn, 0.0f), log1pf(expf(-fabsf(xn))));
        float alphas = fmaxf(1e-5f, sp);
        float aB = __fadd_rn(alphas, 10.0f);

        uint32_t flat = (uint32_t)n * K_DIM + (uint32_t)k;
        float gam = jax_gamma(aB, flat);

        // replicate reference's calc_epsilon -> gamma_h numerical round-trip
        float d  = __fsub_rn(aB, 0.33333334f);
        float sqrt_alpha = sqrtf(__fsub_rn(__fmul_rn(9.0f, aB), 3.0f));
        float powza = powf(__fdiv_rn(gam, d), 0.33333334f);
        float eps = __fmul_rn(sqrt_alpha, __fsub_rn(powza, 1.0f));
        float cc  = __fdiv_rn(1.0f, sqrtf(__fmul_rn(9.0f, d)));
        float vv  = __fadd_rn(1.0f, __fmul_rn(eps, cc));
        float gh  = __fmul_rn(d, __fmul_rn(__fmul_rn(vv, vv), vv));

        float prod = 1.0f;
#pragma unroll
        for (int r = 0; r < NB_AUG; r++) {
            float uu = u[(size_t)r * N_ROWS * K_DIM + (size_t)n * K_DIM + k];
            float av = __fadd_rn(alphas, (float)r);
            float up = __fadd_rn(powf(uu, __fdiv_rn(1.0f, av)), 1e-10f);
            prod = __fmul_rn(prod, up);
        }
        g = __fmul_rn(prod, gh);
    }

    __shared__ float sm[256];
    sm[threadIdx.x] = g;
    __syncthreads();
    for (int st = 128; st > 0; st >>= 1) {
        if (threadIdx.x < st) sm[threadIdx.x] += sm[threadIdx.x + st];
        __syncthreads();
    }
    float rowsum = sm[0];

    if (k < K_DIM)
        out[(size_t)n * K_DIM + k] = __fdiv_rn(g, rowsum);
}

// ---------------- launcher --------------------------------------------------
extern "C" void kernel_launch(void* const* d_in, const int* in_sizes, int n_in,
                              void* d_out, int out_size) {
    const float* hidden = (const float*)d_in[0];   // [16384, 768]
    const float* W      = (const float*)d_in[1];   // [200, 768]
    const float* bias   = (const float*)d_in[2];   // [200]
    const float* u      = (const float*)d_in[3];   // [10, 16384, 200]
    float* out = (float*)d_out;                    // [16384, 200]

    dim3 ggrid((K_DIM + 63) / 64, N_ROWS / 128);   // (4, 128)
    gemm_kernel<<<ggrid, 256>>>(hidden, W, bias);
    colstats_kernel<<<K_DIM, 256>>>();
    main_kernel<<<N_ROWS, 256>>>(u, out);
}

// round 3
// speedup vs baseline: 1.3952x; 1.3952x over previous
#include <cuda_runtime.h>
#include <stdint.h>

#define N_ROWS 16384
#define K_DIM  200
#define H_DIM  768
#define NB_AUG 10

// ---------------- scratch (static device globals; no allocations) ----------
__device__ float g_x[(size_t)N_ROWS * K_DIM];   // fc output
__device__ float g_mu[K_DIM];
__device__ float g_sd[K_DIM];                   // sqrt(var + 1e-5)

// ---------------- threefry2x32 (JAX-exact) ---------------------------------
__device__ __forceinline__ uint2 tf2x32(uint32_t k0, uint32_t k1,
                                        uint32_t x0, uint32_t x1) {
    uint32_t ks2 = k0 ^ k1 ^ 0x1BD11BDAu;
    x0 += k0; x1 += k1;
#define TFR(r) { x0 += x1; x1 = __funnelshift_l(x1, x1, (r)); x1 ^= x0; }
    TFR(13) TFR(15) TFR(26) TFR(6)
    x0 += k1;  x1 += ks2 + 1u;
    TFR(17) TFR(29) TFR(16) TFR(24)
    x0 += ks2; x1 += k0 + 2u;
    TFR(13) TFR(15) TFR(26) TFR(6)
    x0 += k0;  x1 += k1 + 3u;
    TFR(17) TFR(29) TFR(16) TFR(24)
    x0 += k1;  x1 += ks2 + 4u;
    TFR(13) TFR(15) TFR(26) TFR(6)
    x0 += ks2; x1 += k0 + 5u;
#undef TFR
    return make_uint2(x0, x1);
}

// bits -> float in [0,1): ((bits>>9)|0x3f800000) bitcast - 1.0
__device__ __forceinline__ float bits_to_f01(uint32_t bits) {
    return __fsub_rn(__uint_as_float((bits >> 9) | 0x3f800000u), 1.0f);
}

// ---------------- XLA/Giles erfinv (f32), no FMA contraction ---------------
__device__ __forceinline__ float erfinv_xla(float x) {
    float w = -log1pf(-__fmul_rn(x, x));
    float p;
    if (w < 5.0f) {
        w = __fsub_rn(w, 2.5f);
        p = 2.81022636e-08f;
        p = __fadd_rn( 3.43273939e-07f, __fmul_rn(p, w));
        p = __fadd_rn(-3.5233877e-06f,  __fmul_rn(p, w));
        p = __fadd_rn(-4.39150654e-06f, __fmul_rn(p, w));
        p = __fadd_rn( 0.00021858087f,  __fmul_rn(p, w));
        p = __fadd_rn(-0.00125372503f,  __fmul_rn(p, w));
        p = __fadd_rn(-0.00417768164f,  __fmul_rn(p, w));
        p = __fadd_rn( 0.246640727f,    __fmul_rn(p, w));
        p = __fadd_rn( 1.50140941f,     __fmul_rn(p, w));
    } else {
        w = __fsub_rn(sqrtf(w), 3.0f);
        p = -0.000200214257f;
        p = __fadd_rn( 0.000100950558f, __fmul_rn(p, w));
        p = __fadd_rn( 0.00134934322f,  __fmul_rn(p, w));
        p = __fadd_rn(-0.00367342844f,  __fmul_rn(p, w));
        p = __fadd_rn( 0.00573950773f,  __fmul_rn(p, w));
        p = __fadd_rn(-0.0076224613f,   __fmul_rn(p, w));
        p = __fadd_rn( 0.00943887047f,  __fmul_rn(p, w));
        p = __fadd_rn( 1.00167406f,     __fmul_rn(p, w));
        p = __fadd_rn( 2.83297682f,     __fmul_rn(p, w));
    }
    return __fmul_rn(p, x);
}

// scalar normal from a key (JAX: sqrt2 * erfinv(uniform(lo=-0.99999994, hi=1)))
__device__ __forceinline__ float jax_normal_from_key(uint2 k) {
    uint2 nb = tf2x32(k.x, k.y, 0u, 0u);
    float f = bits_to_f01(nb.x ^ nb.y);
    float u = fmaxf(-0.99999994f, __fadd_rn(__fmul_rn(f, 2.0f), -0.99999994f));
    return __fmul_rn(__uint_as_float(0x3FB504F3u) /* sqrt(2) f32 */, erfinv_xla(u));
}

// ---------------- JAX gamma sampler (Marsaglia-Tsang, alpha >= 1) ----------
// flat element index i: per-element key Ki = TF((0,42),(0,i))  [partitionable split]
__device__ float jax_gamma(float aB, uint32_t i) {
    uint2 Ki  = tf2x32(0u, 42u, 0u, i);
    // prologue: key, subkey = split(Ki); subkey feeds unused u_boost (alpha>=1)
    uint2 key = tf2x32(Ki.x, Ki.y, 0u, 0u);

    float d = __fsub_rn(aB, 0.33333334f);
    float c = __fdiv_rn(0.33333334f, sqrtf(d));
    float V = 1.0f;

    for (;;) {
        // key, x_key, U_key = split(key, 3): children (0,0),(0,1),(0,2)
        uint2 xkey = tf2x32(key.x, key.y, 0u, 1u);
        uint2 Ukey = tf2x32(key.x, key.y, 0u, 2u);
        float x, v;
        uint2 ik = xkey;
        for (;;) {
            uint2 sub = tf2x32(ik.x, ik.y, 0u, 1u);  // (chain, subkey) = split(ik)
            x = jax_normal_from_key(sub);
            v = __fadd_rn(1.0f, __fmul_rn(x, c));
            if (v > 0.0f) break;
            ik = tf2x32(ik.x, ik.y, 0u, 0u);         // continue chain (v <= 0)
        }
        float X = __fmul_rn(x, x);
        V = __fmul_rn(__fmul_rn(v, v), v);
        uint2 ub = tf2x32(Ukey.x, Ukey.y, 0u, 0u);
        float U = bits_to_f01(ub.x ^ ub.y);

        // accept if U < 1 - 0.0331*X^2  (squeeze)
        float sq = __fsub_rn(1.0f, __fmul_rn(0.0331f, __fmul_rn(X, X)));
        if (U < sq) break;
        // accept if log U < 0.5*X + d - d*V + d*log V
        float rhs = __fadd_rn(__fmul_rn(X, 0.5f),
                    __fadd_rn(__fsub_rn(d, __fmul_rn(d, V)), __fmul_rn(d, logf(V))));
        if (logf(U) < rhs) break;
        key = tf2x32(key.x, key.y, 0u, 0u);          // reject: continue outer chain
    }
    float z = __fmul_rn(d, V);
    return (z == 0.0f) ? 1.17549435e-38f : z;
}

// ---------------- SGEMM: g_x = hidden(16384x768) * W(200x768)^T + b --------
// 128x128 block tile, 8x8 per-thread microtile, BK=16, double-buffered smem.
// Per-output FMA chain iterates k=0..767 monotonically with one accumulator
// => bitwise-identical to R1's x (decision path preserved).
__global__ void __launch_bounds__(256)
gemm_kernel(const float* __restrict__ A, const float* __restrict__ Wm,
            const float* __restrict__ bias) {
    const int BM = 128, BN = 128, BK = 16;
    __shared__ float As[2][BK][BM];
    __shared__ float Bs[2][BK][BN];

    const int m0 = blockIdx.y * BM;
    const int n0 = blockIdx.x * BN;
    const int tid = threadIdx.x;
    const int tx = tid & 15;    // n-dir, 0..15
    const int ty = tid >> 4;    // m-dir, 0..15

    // global-load mapping: each thread loads 2 float4 for A, 2 for B per tile
    // idx = tid*2+q  (0..511): r = idx>>2 (0..127), c4 = idx&3 (0..3)
    const int ra0 = (tid * 2) >> 2, ca0 = (tid * 2) & 3;
    const int ra1 = (tid * 2 + 1) >> 2, ca1 = (tid * 2 + 1) & 3;

    float acc[8][8];
#pragma unroll
    for (int i = 0; i < 8; i++)
#pragma unroll
        for (int j = 0; j < 8; j++) acc[i][j] = 0.0f;

    const bool bv0ok = (n0 + ra0) < K_DIM;
    const bool bv1ok = (n0 + ra1) < K_DIM;

    // ---- load tile 0 into buffer 0 ----
    {
        float4 a0 = *reinterpret_cast<const float4*>(&A[(size_t)(m0 + ra0) * H_DIM + ca0 * 4]);
        float4 a1 = *reinterpret_cast<const float4*>(&A[(size_t)(m0 + ra1) * H_DIM + ca1 * 4]);
        float4 b0 = make_float4(0.f,0.f,0.f,0.f), b1 = make_float4(0.f,0.f,0.f,0.f);
        if (bv0ok) b0 = *reinterpret_cast<const float4*>(&Wm[(size_t)(n0 + ra0) * H_DIM + ca0 * 4]);
        if (bv1ok) b1 = *reinterpret_cast<const float4*>(&Wm[(size_t)(n0 + ra1) * H_DIM + ca1 * 4]);
        As[0][ca0*4+0][ra0]=a0.x; As[0][ca0*4+1][ra0]=a0.y; As[0][ca0*4+2][ra0]=a0.z; As[0][ca0*4+3][ra0]=a0.w;
        As[0][ca1*4+0][ra1]=a1.x; As[0][ca1*4+1][ra1]=a1.y; As[0][ca1*4+2][ra1]=a1.z; As[0][ca1*4+3][ra1]=a1.w;
        Bs[0][ca0*4+0][ra0]=b0.x; Bs[0][ca0*4+1][ra0]=b0.y; Bs[0][ca0*4+2][ra0]=b0.z; Bs[0][ca0*4+3][ra0]=b0.w;
        Bs[0][ca1*4+0][ra1]=b1.x; Bs[0][ca1*4+1][ra1]=b1.y; Bs[0][ca1*4+2][ra1]=b1.z; Bs[0][ca1*4+3][ra1]=b1.w;
    }
    __syncthreads();

    int buf = 0;
    for (int t = 1; t <= H_DIM / BK; t++) {
        float4 a0, a1, b0, b1;
        const bool more = (t < H_DIM / BK);
        if (more) {
            const int h0 = t * BK;
            a0 = *reinterpret_cast<const float4*>(&A[(size_t)(m0 + ra0) * H_DIM + h0 + ca0 * 4]);
            a1 = *reinterpret_cast<const float4*>(&A[(size_t)(m0 + ra1) * H_DIM + h0 + ca1 * 4]);
            b0 = make_float4(0.f,0.f,0.f,0.f); b1 = make_float4(0.f,0.f,0.f,0.f);
            if (bv0ok) b0 = *reinterpret_cast<const float4*>(&Wm[(size_t)(n0 + ra0) * H_DIM + h0 + ca0 * 4]);
            if (bv1ok) b1 = *reinterpret_cast<const float4*>(&Wm[(size_t)(n0 + ra1) * H_DIM + h0 + ca1 * 4]);
        }
        // compute on current buffer
#pragma unroll
        for (int kk = 0; kk < BK; kk++) {
            float af[8], bf[8];
#pragma unroll
            for (int q = 0; q < 2; q++) {
                float4 v = *reinterpret_cast<const float4*>(&As[buf][kk][ty * 8 + q * 4]);
                af[q*4+0]=v.x; af[q*4+1]=v.y; af[q*4+2]=v.z; af[q*4+3]=v.w;
                float4 w = *reinterpret_cast<const float4*>(&Bs[buf][kk][tx * 8 + q * 4]);
                bf[q*4+0]=w.x; bf[q*4+1]=w.y; bf[q*4+2]=w.z; bf[q*4+3]=w.w;
            }
#pragma unroll
            for (int i = 0; i < 8; i++)
#pragma unroll
                for (int j = 0; j < 8; j++)
                    acc[i][j] = fmaf(af[i], bf[j], acc[i][j]);
        }
        if (more) {
            int nb = buf ^ 1;
            As[nb][ca0*4+0][ra0]=a0.x; As[nb][ca0*4+1][ra0]=a0.y; As[nb][ca0*4+2][ra0]=a0.z; As[nb][ca0*4+3][ra0]=a0.w;
            As[nb][ca1*4+0][ra1]=a1.x; As[nb][ca1*4+1][ra1]=a1.y; As[nb][ca1*4+2][ra1]=a1.z; As[nb][ca1*4+3][ra1]=a1.w;
            Bs[nb][ca0*4+0][ra0]=b0.x; Bs[nb][ca0*4+1][ra0]=b0.y; Bs[nb][ca0*4+2][ra0]=b0.z; Bs[nb][ca0*4+3][ra0]=b0.w;
            Bs[nb][ca1*4+0][ra1]=b1.x; Bs[nb][ca1*4+1][ra1]=b1.y; Bs[nb][ca1*4+2][ra1]=b1.z; Bs[nb][ca1*4+3][ra1]=b1.w;
            __syncthreads();
            buf = nb;
        }
    }

#pragma unroll
    for (int i = 0; i < 8; i++) {
        const int m = m0 + ty * 8 + i;
#pragma unroll
        for (int j = 0; j < 8; j++) {
            const int nn = n0 + tx * 8 + j;
            if (nn < K_DIM)
                g_x[(size_t)m * K_DIM + nn] = acc[i][j] + bias[nn];
        }
    }
}

// ---------------- per-column mean / std (two-pass, like jnp.mean/var) ------
// NOTE: summation order is decision-coupled (var -> xn -> alpha -> rejection
// decisions). This exact order passed; do not reorder.
__global__ void __launch_bounds__(256) colstats_kernel() {
    int k = blockIdx.x;
    int t = threadIdx.x;
    __shared__ float sm[256];
    float s = 0.0f;
    for (int n = t; n < N_ROWS; n += 256) s += g_x[(size_t)n * K_DIM + k];
    sm[t] = s; __syncthreads();
    for (int st = 128; st > 0; st >>= 1) {
        if (t < st) sm[t] += sm[t + st];
        __syncthreads();
    }
    float mu = sm[0] / 16384.0f;
    __syncthreads();
    float v = 0.0f;
    for (int n = t; n < N_ROWS; n += 256) {
        float dd = g_x[(size_t)n * K_DIM + k] - mu;
        v += dd * dd;
    }
    sm[t] = v; __syncthreads();
    for (int st = 128; st > 0; st >>= 1) {
        if (t < st) sm[t] += sm[t + st];
        __syncthreads();
    }
    if (t == 0) {
        g_mu[k] = mu;
        g_sd[k] = sqrtf(sm[0] / 16384.0f + 1e-5f);
    }
}

// ---------------- fused: softplus -> gamma -> u-pow product -> rownorm -----
__global__ void __launch_bounds__(256)
main_kernel(const float* __restrict__ u, float* __restrict__ out) {
    int n = blockIdx.x;
    int k = threadIdx.x;
    float g = 0.0f;

    if (k < K_DIM) {
        float xv = g_x[(size_t)n * K_DIM + k];
        float xn = __fdiv_rn(__fsub_rn(xv, g_mu[k]), g_sd[k]);
        // softplus = max(x,0) + log1p(exp(-|x|))   (decision path: exact)
        float sp = __fadd_rn(fmaxf(xn, 0.0f), log1pf(expf(-fabsf(xn))));
        float alphas = fmaxf(1e-5f, sp);
        float aB = __fadd_rn(alphas, 10.0f);

        uint32_t flat = (uint32_t)n * K_DIM + (uint32_t)k;
        float gam = jax_gamma(aB, flat);
        // gamma_h(calc_epsilon(gam,aB),aB) == gam mathematically; the
        // reference's numerical round-trip differs by ~3e-7 rel (output
        // path only) -- skip it.

        float prod = 1.0f;
#pragma unroll
        for (int r = 0; r < NB_AUG; r++) {
            float uu = u[(size_t)r * N_ROWS * K_DIM + (size_t)n * K_DIM + k];
            float av = __fadd_rn(alphas, (float)r);
            // output path: fast pow (MUFU lg2/ex2) is ~1e-6 rel, fine
            float up = __fadd_rn(__powf(uu, __fdividef(1.0f, av)), 1e-10f);
            prod = __fmul_rn(prod, up);
        }
        g = __fmul_rn(prod, gam);
    }

    __shared__ float sm[256];
    sm[threadIdx.x] = g;
    __syncthreads();
    for (int st = 128; st > 0; st >>= 1) {
        if (threadIdx.x < st) sm[threadIdx.x] += sm[threadIdx.x + st];
        __syncthreads();
    }
    float rowsum = sm[0];

    if (k < K_DIM)
        out[(size_t)n * K_DIM + k] = __fdiv_rn(g, rowsum);
}

// ---------------- launcher --------------------------------------------------
extern "C" void kernel_launch(void* const* d_in, const int* in_sizes, int n_in,
                              void* d_out, int out_size) {
    const float* hidden = (const float*)d_in[0];   // [16384, 768]
    const float* W      = (const float*)d_in[1];   // [200, 768]
    const float* bias   = (const float*)d_in[2];   // [200]
    const float* u      = (const float*)d_in[3];   // [10, 16384, 200]
    float* out = (float*)d_out;                    // [16384, 200]

    dim3 ggrid((K_DIM + 127) / 128, N_ROWS / 128); // (2, 128)
    gemm_kernel<<<ggrid, 256>>>(hidden, W, bias);
    colstats_kernel<<<K_DIM, 256>>>();
    main_kernel<<<N_ROWS, 256>>>(u, out);
}